// round 7
// baseline (speedup 1.0000x reference)
#include <cuda_runtime.h>

// Problem constants (match reference)
#define NUM_CH   5
#define CROP_LO  70      // D//2 - 16, D = 173
#define CROP_HI  101     // CROP_LO + 32 - 1
#define CROP_N   32
#define CUBES    5
#define LATO     11      // 2*CUBES+1
#define RES2     0.0625f // RES*RES

#define SLABS    8       // x-slabs of width 4 -> 40*8 = 320 blocks
#define SLAB_X   4
#define MAX_N    256     // max atoms per batch supported

// ONE kernel, one graph node. Each block exclusively owns one
// (batch, channel, 4-wide x-slab) region (16KB) of the output:
// zero it, build a compacted worklist of intersecting same-channel atoms,
// splat each atom's clipped cells across all 128 threads (<=4 iters/atom).
__global__ void __launch_bounds__(128) fused_voxelize_kernel(
    const float* __restrict__ coords,        // [B, N, 3]
    const int*   __restrict__ atoms_channel, // [B, N]
    const float* __restrict__ radius,        // [B, N]
    float* __restrict__ out,                 // [B, NUM_CH, 32, 32, 32]
    int n_per_batch)
{
    __shared__ int    s_cnt;
    // packed per-slot params: [0]=fx [1]=fy [2]=fz [3]=coef
    __shared__ float4 s_f[MAX_N];
    // [0]=ntot [1]=nyz [2]=nz [3]=offset
    __shared__ int4   s_i[MAX_N];
    __shared__ float2 s_r[MAX_N];   // rnyz, rnz

    const int tid  = threadIdx.x;
    const int bc   = blockIdx.x;          // b * NUM_CH + ch  (0..39)
    const int slab = blockIdx.y;          // 0..7
    const int b    = bc / NUM_CH;
    const int ch   = bc - b * NUM_CH;

    const int xs    = slab * SLAB_X;              // slab x start (crop coords)
    const int sx_lo = CROP_LO + xs;
    const int sx_hi = sx_lo + SLAB_X - 1;

    // --- preload atom data into registers (parallel, overlaps the zeroing) ---
    float cx = 0.f, cy = 0.f, cz = 0.f, r = 1.f;
    int   c  = -1;
    const bool has_atom = (tid < n_per_batch);
    if (has_atom) {
        const int atom = b * n_per_batch + tid;
        cx = coords[3 * atom + 0];
        cy = coords[3 * atom + 1];
        cz = coords[3 * atom + 2];
        r  = radius[atom];
        c  = atoms_channel[atom];
    }
    if (tid == 0) s_cnt = 0;

    // --- zero this block's exclusive 16KB global slab (contiguous, float4) ---
    float* vol = out + (size_t)bc * (CROP_N * CROP_N * CROP_N);
    float4* dst = (float4*)(vol + xs * (CROP_N * CROP_N));
    #pragma unroll
    for (int i = 0; i < SLAB_X * CROP_N * CROP_N / 4 / 128; ++i)   // 8 iters
        dst[tid + i * 128] = make_float4(0.f, 0.f, 0.f, 0.f);

    __syncthreads();   // s_cnt visible; zeros ordered before our REDs (CTA scope)

    // --- derive + compact worklist (threads 0..n-1) ---
    if (has_atom && c == ch) {
        // scaled = (c + BOX)/RES + (CUBES+1); /0.25 == *4 exactly
        const float sx = (cx + 20.0f) * 4.0f + 6.0f;
        const float sy = (cy + 20.0f) * 4.0f + 6.0f;
        const float sz = (cz + 20.0f) * 4.0f + 6.0f;
        const int bx = (int)floorf(sx) - CUBES;
        const int by = (int)floorf(sy) - CUBES;
        const int bz = (int)floorf(sz) - CUBES;

        const int x0 = max(0, sx_lo  - bx), x1 = min(LATO - 1, sx_hi  - bx);
        const int y0 = max(0, CROP_LO - by), y1 = min(LATO - 1, CROP_HI - by);
        const int z0 = max(0, CROP_LO - bz), z1 = min(LATO - 1, CROP_HI - bz);
        const int nx = x1 - x0 + 1, ny = y1 - y0 + 1, nz = z1 - z0 + 1;

        if (nx > 0 && ny > 0 && nz > 0) {
            const int slot = atomicAdd(&s_cnt, 1);
            const int nyz = ny * nz;
            s_f[slot] = make_float4(sx - (float)(bx + x0) - 0.5f,
                                    sy - (float)(by + y0) - 0.5f,
                                    sz - (float)(bz + z0) - 0.5f,
                                    0.5f * RES2 / (r * r));
            s_i[slot] = make_int4(nx * nyz, nyz, nz,
                                  ((bx + x0 - CROP_LO) * CROP_N + (by + y0 - CROP_LO)) * CROP_N
                                   + (bz + z0 - CROP_LO));
            s_r[slot] = make_float2(1.0f / (float)nyz, 1.0f / (float)nz);
        }
    }
    __syncthreads();

    // --- splat: sequential over worklist, cell-parallel over 128 threads ---
    const int cnt = s_cnt;
    for (int i = 0; i < cnt; ++i) {
        const float4 f  = s_f[i];
        const int4   ii = s_i[i];
        const float2 rr = s_r[i];
        const int   ntot = ii.x, nyz = ii.y, nz = ii.z;
        float* __restrict__ p = vol + ii.w;

        for (int k = tid; k < ntot; k += 128) {
            // exact small-int division via fp32 (k < 484, divisors <= 121)
            int ox  = (int)(((float)k + 0.5f) * rr.x);
            int rem = k - ox * nyz;
            int oy  = (int)(((float)rem + 0.5f) * rr.y);
            int oz  = rem - oy * nz;
            float dx = f.x - (float)ox;
            float dy = f.y - (float)oy;
            float dz = f.z - (float)oz;
            float d2 = fmaf(dx, dx, fmaf(dy, dy, dz * dz));
            float v  = __expf(-f.w * d2);
            atomicAdd(&p[(ox * CROP_N + oy) * CROP_N + oz], v);
        }
    }
}

extern "C" void kernel_launch(void* const* d_in, const int* in_sizes, int n_in,
                              void* d_out, int out_size) {
    const float* coords        = (const float*)d_in[0]; // [B,N,3]
    const int*   atoms_channel = (const int*)d_in[1];   // [B,N]
    const float* radius        = (const float*)d_in[2]; // [B,N]
    float* out = (float*)d_out;

    int n_atoms = in_sizes[1];                               // B*N = 512
    int B = out_size / (NUM_CH * CROP_N * CROP_N * CROP_N);  // 8
    int n_per_batch = n_atoms / B;                           // 64

    dim3 grid(B * NUM_CH, SLABS);                            // 40 x 8 = 320 blocks
    fused_voxelize_kernel<<<grid, 128>>>(coords, atoms_channel, radius, out,
                                         n_per_batch);
}